// round 3
// baseline (speedup 1.0000x reference)
#include <cuda_runtime.h>
#include <cuda_bf16.h>
#include <cstdint>

// ----------------------------------------------------------------------------
// Problem constants
// ----------------------------------------------------------------------------
#define DIM 128            // input dim d
#define BATCH 4096
#define HID 512            // 2*OUTPUT_DIM
#define OUTD 256
#define KTOT (DIM * DIM)   // 16384
#define KC 64              // K chunk per cp.async stage
#define NCHUNK (KTOT / KC) // 256

#define XS_STRIDE 132      // padded x-tile row stride (floats)
#define BS_STRIDE 136      // padded B-tile row stride (floats)
#define BS_BUF_FLOATS (KC * BS_STRIDE)          // 8704 floats = 34816 B
#define SM_XS_FLOATS (128 * XS_STRIDE)          // 16896 floats = 67584 B
#define G1_SMEM_BYTES ((SM_XS_FLOATS + 2 * BS_BUF_FLOATS) * 4)  // 137216 B

// ----------------------------------------------------------------------------
// Device scratch (static allocation: allowed)
// ----------------------------------------------------------------------------
__device__ float g_w1c[KTOT * HID];      // W1 rounded to tf32, same [k][n] layout (33.5MB)
__device__ float g_h[BATCH * HID];       // hidden activations (8MB)

// ----------------------------------------------------------------------------
// Helpers
// ----------------------------------------------------------------------------
__device__ __forceinline__ uint32_t smem_u32(const void* p) {
    uint32_t a;
    asm("{ .reg .u64 t; cvta.to.shared.u64 t, %1; cvt.u32.u64 %0, t; }" : "=r"(a) : "l"(p));
    return a;
}
__device__ __forceinline__ uint32_t f2tf32(float f) {
    uint32_t r;
    asm("cvt.rna.tf32.f32 %0, %1;" : "=r"(r) : "f"(f));
    return r;
}
__device__ __forceinline__ void cp_async16(uint32_t smem_addr, const void* gptr) {
    asm volatile("cp.async.cg.shared.global [%0], [%1], 16;" :: "r"(smem_addr), "l"(gptr) : "memory");
}
#define CP_COMMIT() asm volatile("cp.async.commit_group;" ::: "memory")
#define CP_WAIT(n)  asm volatile("cp.async.wait_group %0;" :: "n"(n) : "memory")

// mma.sync m16n8k8 tf32: D += A * B  (row.col, f32 accum)
#define MMA_TF32(d, a, bb0, bb1) \
    asm volatile("mma.sync.aligned.m16n8k8.row.col.f32.tf32.tf32.f32 " \
        "{%0,%1,%2,%3}, {%4,%5,%6,%7}, {%8,%9}, {%0,%1,%2,%3};" \
        : "+f"((d)[0]), "+f"((d)[1]), "+f"((d)[2]), "+f"((d)[3]) \
        : "r"((a)[0]), "r"((a)[1]), "r"((a)[2]), "r"((a)[3]), "r"(bb0), "r"(bb1))

// ----------------------------------------------------------------------------
// Kernel 1: round W1 to tf32 (same layout)
// ----------------------------------------------------------------------------
__global__ __launch_bounds__(256) void k_w1_cvt(const float* __restrict__ W1) {
    size_t i = ((size_t)blockIdx.x * 256 + threadIdx.x) * 4;
    float4 v = *(const float4*)(W1 + i);
    v.x = __uint_as_float(f2tf32(v.x));
    v.y = __uint_as_float(f2tf32(v.y));
    v.z = __uint_as_float(f2tf32(v.z));
    v.w = __uint_as_float(f2tf32(v.w));
    *(float4*)(g_w1c + i) = v;
}

// ----------------------------------------------------------------------------
// Kernel 2: H = relu( (d * x (x) x) @ W1 + b1 )  via mma.sync tf32
//   Grid: 128 CTAs = 32 M-tiles x 4 N-tiles (128x128 each). 256 threads.
//   Warp tile 32(m) x 64(n). A generated in registers from SMEM x-tile.
// ----------------------------------------------------------------------------
__global__ __launch_bounds__(256, 1) void k_gemm1(const float* __restrict__ x,
                                                  const float* __restrict__ b1) {
    extern __shared__ char smem_raw[];
    float* xs = (float*)smem_raw;                       // [128][XS_STRIDE]
    float* bs = xs + SM_XS_FLOATS;                      // 2 x [KC][BS_STRIDE]
    const uint32_t sb_bs = smem_u32(bs);

    const int tid  = threadIdx.x;
    const int lane = tid & 31;
    const int wid  = tid >> 5;
    const int wm   = wid & 3;        // 0..3 : 32-row slab
    const int wn   = wid >> 2;       // 0..1 : 64-col slab
    const int m0 = (blockIdx.x & 31) * 128;
    const int n0 = (blockIdx.x >> 5) * 128;

    const int r0 = lane >> 2;        // 0..7
    const int c0 = lane & 3;         // 0..3

    // ---- issue cp.async for chunk 0 (buf 0) before x staging, to overlap ----
    const float* w1g = g_w1c;
    {
        #pragma unroll
        for (int r = 0; r < 8; r++) {
            int id = tid + r * 256;          // 0..2047
            int kr = id >> 5;                // 0..63
            int seg = id & 31;               // 0..31 (16B pieces of 512B row)
            cp_async16(sb_bs + (uint32_t)(kr * (BS_STRIDE * 4) + seg * 16),
                       w1g + (size_t)kr * HID + n0 + seg * 4);
        }
        CP_COMMIT();
    }

    // ---- stage x tile: rows m0..m0+127, padded stride ----
    #pragma unroll
    for (int r = 0; r < 16; r++) {
        int id = tid + r * 256;              // 0..4095 float4s
        int m = id >> 5, c4 = id & 31;
        float4 v = *(const float4*)(x + (size_t)(m0 + m) * DIM + c4 * 4);
        *(float4*)(xs + m * XS_STRIDE + c4 * 4) = v;
    }
    __syncthreads();

    // thread's 4 m-rows (local to CTA tile)
    int rows[4];
    rows[0] = wm * 32 + r0;
    rows[1] = rows[0] + 8;
    rows[2] = rows[0] + 16;
    rows[3] = rows[0] + 24;

    float acc[2][8][4];
    #pragma unroll
    for (int mt = 0; mt < 2; mt++)
        #pragma unroll
        for (int nt = 0; nt < 8; nt++)
            #pragma unroll
            for (int q = 0; q < 4; q++) acc[mt][nt][q] = 0.0f;

    #pragma unroll 1
    for (int it = 0; it < NCHUNK; it++) {
        // prefetch next chunk into the other buffer
        if (it + 1 < NCHUNK) {
            const int nb = (it + 1) & 1;
            const int kbase = (it + 1) * KC;
            #pragma unroll
            for (int r = 0; r < 8; r++) {
                int id = tid + r * 256;
                int kr = id >> 5;
                int seg = id & 31;
                cp_async16(sb_bs + (uint32_t)(nb * (BS_BUF_FLOATS * 4) + kr * (BS_STRIDE * 4) + seg * 16),
                           w1g + (size_t)(kbase + kr) * HID + n0 + seg * 4);
            }
            CP_COMMIT();
            CP_WAIT(1);
        } else {
            CP_WAIT(0);
        }
        __syncthreads();

        const float* bsf = bs + (it & 1) * BS_BUF_FLOATS;
        const int i_idx = it >> 1;           // 0..127
        const int j0 = (it & 1) << 6;        // 0 or 64

        // xi * d, per thread-row (i fixed for the whole chunk)
        float xi[4];
        #pragma unroll
        for (int t = 0; t < 4; t++)
            xi[t] = xs[rows[t] * XS_STRIDE + i_idx] * 128.0f;

        #pragma unroll
        for (int s = 0; s < 8; s++) {        // 8 k-steps of 8
            const int jb = j0 + s * 8;
            // ---- A fragments (2 m16 tiles), computed in registers ----
            uint32_t afrag[2][4];
            #pragma unroll
            for (int mt = 0; mt < 2; mt++) {
                float xjA0 = xs[rows[2 * mt + 0] * XS_STRIDE + jb + c0];
                float xjB0 = xs[rows[2 * mt + 1] * XS_STRIDE + jb + c0];
                float xjA1 = xs[rows[2 * mt + 0] * XS_STRIDE + jb + c0 + 4];
                float xjB1 = xs[rows[2 * mt + 1] * XS_STRIDE + jb + c0 + 4];
                afrag[mt][0] = f2tf32(xi[2 * mt + 0] * xjA0);
                afrag[mt][1] = f2tf32(xi[2 * mt + 1] * xjB0);
                afrag[mt][2] = f2tf32(xi[2 * mt + 0] * xjA1);
                afrag[mt][3] = f2tf32(xi[2 * mt + 1] * xjB1);
            }
            // ---- B fragments (8 n8 tiles) ----
            const float* bp = bsf + (s * 8 + c0) * BS_STRIDE + wn * 64 + r0;
            uint32_t bfr0[8], bfr1[8];
            #pragma unroll
            for (int nt = 0; nt < 8; nt++) {
                bfr0[nt] = __float_as_uint(bp[nt * 8]);
                bfr1[nt] = __float_as_uint(bp[4 * BS_STRIDE + nt * 8]);
            }
            // ---- MMAs ----
            #pragma unroll
            for (int mt = 0; mt < 2; mt++)
                #pragma unroll
                for (int nt = 0; nt < 8; nt++)
                    MMA_TF32(acc[mt][nt], afrag[mt], bfr0[nt], bfr1[nt]);
        }
        __syncthreads();
    }

    // ---- Epilogue: +b1, relu, store to g_h ----
    #pragma unroll
    for (int mt = 0; mt < 2; mt++) {
        #pragma unroll
        for (int nt = 0; nt < 8; nt++) {
            int col = n0 + wn * 64 + nt * 8 + c0 * 2;
            float bb0 = b1[col], bb1 = b1[col + 1];
            int rowA = m0 + wm * 32 + mt * 16 + r0;
            float2 v0 = make_float2(fmaxf(acc[mt][nt][0] + bb0, 0.0f),
                                    fmaxf(acc[mt][nt][1] + bb1, 0.0f));
            float2 v1 = make_float2(fmaxf(acc[mt][nt][2] + bb0, 0.0f),
                                    fmaxf(acc[mt][nt][3] + bb1, 0.0f));
            *(float2*)(g_h + (size_t)rowA * HID + col) = v0;
            *(float2*)(g_h + (size_t)(rowA + 8) * HID + col) = v1;
        }
    }
}

// ----------------------------------------------------------------------------
// Kernel 3: out = h @ W2 + b2   [4096,512]x[512,256]
// ----------------------------------------------------------------------------
#define FMA2(acc, a, b) \
    asm("fma.rn.f32x2 %0, %1, %2, %0;" : "+l"(acc) : "l"(a), "l"(b))

__global__ __launch_bounds__(256) void k_layer2(const float* __restrict__ W2,
                                                const float* __restrict__ b2,
                                                float* __restrict__ out) {
    __shared__ float w2s[32 * 256];
    __shared__ float hs[32 * 32];
    const int tid = threadIdx.x;
    const int l = tid & 31;
    const int w = tid >> 5;
    const int m0 = blockIdx.x * 32;
    unsigned long long acc[4][4] = {};

    #pragma unroll 1
    for (int ch = 0; ch < 16; ch++) {
        #pragma unroll
        for (int r = 0; r < 8; r++) {
            int id = tid + r * 256;
            int rr = id >> 6, c4 = id & 63;
            *(float4*)(w2s + rr * 256 + c4 * 4) =
                *(const float4*)(W2 + (size_t)(ch * 32 + rr) * 256 + c4 * 4);
        }
        {
            int bl = tid >> 3, c4 = tid & 7;
            *(float4*)(hs + bl * 32 + c4 * 4) =
                *(const float4*)(g_h + (size_t)(m0 + bl) * HID + ch * 32 + c4 * 4);
        }
        __syncthreads();
        #pragma unroll 4
        for (int cc = 0; cc < 32; cc++) {
            ulonglong2 wA = *(const ulonglong2*)(w2s + cc * 256 + l * 4);
            ulonglong2 wB = *(const ulonglong2*)(w2s + cc * 256 + 128 + l * 4);
            #pragma unroll
            for (int bi = 0; bi < 4; bi++) {
                float hv = hs[(w * 4 + bi) * 32 + cc];
                unsigned long long hp;
                asm("mov.b64 %0, {%1, %1};" : "=l"(hp) : "f"(hv));
                FMA2(acc[bi][0], hp, wA.x);
                FMA2(acc[bi][1], hp, wA.y);
                FMA2(acc[bi][2], hp, wB.x);
                FMA2(acc[bi][3], hp, wB.y);
            }
        }
        __syncthreads();
    }
    float bA0 = b2[l * 4 + 0], bA1 = b2[l * 4 + 1], bA2 = b2[l * 4 + 2], bA3 = b2[l * 4 + 3];
    float bB0 = b2[128 + l * 4 + 0], bB1 = b2[128 + l * 4 + 1];
    float bB2 = b2[128 + l * 4 + 2], bB3 = b2[128 + l * 4 + 3];
    #pragma unroll
    for (int bi = 0; bi < 4; bi++) {
        int row = m0 + w * 4 + bi;
        float* orow = out + (size_t)row * 256;
        float f0, f1;
        asm("mov.b64 {%0, %1}, %2;" : "=f"(f0), "=f"(f1) : "l"(acc[bi][0]));
        *(float2*)(orow + l * 4) = make_float2(f0 + bA0, f1 + bA1);
        asm("mov.b64 {%0, %1}, %2;" : "=f"(f0), "=f"(f1) : "l"(acc[bi][1]));
        *(float2*)(orow + l * 4 + 2) = make_float2(f0 + bA2, f1 + bA3);
        asm("mov.b64 {%0, %1}, %2;" : "=f"(f0), "=f"(f1) : "l"(acc[bi][2]));
        *(float2*)(orow + 128 + l * 4) = make_float2(f0 + bB0, f1 + bB1);
        asm("mov.b64 {%0, %1}, %2;" : "=f"(f0), "=f"(f1) : "l"(acc[bi][3]));
        *(float2*)(orow + 128 + l * 4 + 2) = make_float2(f0 + bB2, f1 + bB3);
    }
}

// ----------------------------------------------------------------------------
// Launch
// ----------------------------------------------------------------------------
extern "C" void kernel_launch(void* const* d_in, const int* in_sizes, int n_in,
                              void* d_out, int out_size) {
    const float *x = nullptr, *W1 = nullptr, *b1 = nullptr, *W2 = nullptr, *b2 = nullptr;
    for (int i = 0; i < n_in; i++) {
        switch (in_sizes[i]) {
            case BATCH * DIM:  x  = (const float*)d_in[i]; break;   // 524288
            case KTOT * HID:   W1 = (const float*)d_in[i]; break;   // 8388608
            case HID:          b1 = (const float*)d_in[i]; break;   // 512
            case HID * OUTD:   W2 = (const float*)d_in[i]; break;   // 131072
            case OUTD:         b2 = (const float*)d_in[i]; break;   // 256
            default: break;
        }
    }

    cudaFuncSetAttribute(k_gemm1, cudaFuncAttributeMaxDynamicSharedMemorySize, G1_SMEM_BYTES);

    k_w1_cvt<<<KTOT * HID / (256 * 4), 256>>>(W1);
    k_gemm1<<<128, 256, G1_SMEM_BYTES>>>(x, b1);
    k_layer2<<<BATCH / 32, 256>>>(W2, b2, (float*)d_out);
}

// round 4
// speedup vs baseline: 2.3266x; 2.3266x over previous
#include <cuda_runtime.h>
#include <cuda_fp16.h>
#include <cstdint>

// ----------------------------------------------------------------------------
// Problem constants
// ----------------------------------------------------------------------------
#define DIM 128            // input dim d
#define BATCH 4096
#define HID 512            // 2*OUTPUT_DIM
#define OUTD 256
#define KTOT (DIM * DIM)   // 16384
#define KC 64              // K chunk per cp.async stage
#define NCHUNK (KTOT / KC) // 256

// GEMM1 tiling: CTA 128(M) x 64(N), 8 warps (warp tile 32x32), 256 CTAs
#define XS_STRIDE 136      // fp16 x-tile row stride (halfs)  -> conflict-free
#define BS_STRIDE 72       // fp16 B-stage row stride (halfs) -> conflict-free
#define XS_HALFS (128 * XS_STRIDE)           // 17408 halfs = 34816 B
#define BS_STAGE_HALFS (KC * BS_STRIDE)      // 4608 halfs  = 9216 B
#define G1_SMEM_BYTES ((XS_HALFS + 2 * BS_STAGE_HALFS) * 2)   // 53248 B

// ----------------------------------------------------------------------------
// Device scratch (static allocation: allowed)
// ----------------------------------------------------------------------------
__device__ __half g_w1t[HID * KTOT];     // W1^T in fp16, [n][k] layout (16.8MB)
__device__ float  g_h[BATCH * HID];      // hidden activations (8MB)

// ----------------------------------------------------------------------------
// Helpers
// ----------------------------------------------------------------------------
__device__ __forceinline__ uint32_t smem_u32(const void* p) {
    uint32_t a;
    asm("{ .reg .u64 t; cvta.to.shared.u64 t, %1; cvt.u32.u64 %0, t; }" : "=r"(a) : "l"(p));
    return a;
}
__device__ __forceinline__ void cp_async16(uint32_t smem_addr, const void* gptr) {
    asm volatile("cp.async.cg.shared.global [%0], [%1], 16;" :: "r"(smem_addr), "l"(gptr) : "memory");
}
#define CP_COMMIT() asm volatile("cp.async.commit_group;" ::: "memory")
#define CP_WAIT(n)  asm volatile("cp.async.wait_group %0;" :: "n"(n) : "memory")

// mma.sync m16n8k16 fp16, f32 accumulate (row.col)
#define MMA_F16(d, a, bb0, bb1) \
    asm volatile("mma.sync.aligned.m16n8k16.row.col.f32.f16.f16.f32 " \
        "{%0,%1,%2,%3}, {%4,%5,%6,%7}, {%8,%9}, {%0,%1,%2,%3};" \
        : "+f"((d)[0]), "+f"((d)[1]), "+f"((d)[2]), "+f"((d)[3]) \
        : "r"((a)[0]), "r"((a)[1]), "r"((a)[2]), "r"((a)[3]), "r"(bb0), "r"(bb1))

// ----------------------------------------------------------------------------
// Kernel 1: W1 [16384][512] f32  ->  g_w1t [512][16384] fp16 (transpose + cvt)
//   block (32,8), each block does a 64(k) x 32(n) tile.
// ----------------------------------------------------------------------------
__global__ __launch_bounds__(256) void k_w1t(const float* __restrict__ W1) {
    __shared__ float t[32][66];          // [n][k-pair-padded]
    const int kb = blockIdx.x * 64;
    const int nb = blockIdx.y * 32;
    const int tx = threadIdx.x, ty = threadIdx.y;
    #pragma unroll
    for (int r = 0; r < 8; r++) {
        int k = ty + r * 8;              // 0..63
        t[tx][k] = W1[(size_t)(kb + k) * HID + nb + tx];
    }
    __syncthreads();
    #pragma unroll
    for (int r = 0; r < 4; r++) {
        int n = ty + r * 8;              // 0..31
        __half2 h = __floats2half2_rn(t[n][tx * 2], t[n][tx * 2 + 1]);
        *(__half2*)(g_w1t + (size_t)(nb + n) * KTOT + kb + tx * 2) = h;
    }
}

// ----------------------------------------------------------------------------
// Kernel 2: H = relu( (d * x (x) x) @ W1 + b1 )   via fp16 mma, f32 accum.
//   A-operand = fp16(x_j) (no per-k math); per 128-k i-block, partial sums
//   are rescaled by exact f32 (128*x_i) into the final accumulators.
//   Grid 256 = 32 M-tiles(128) x 8 N-tiles(64).  256 thr, 2 CTAs/SM.
// ----------------------------------------------------------------------------
__global__ __launch_bounds__(256, 2) void k_gemm1(const float* __restrict__ x,
                                                  const float* __restrict__ bias1) {
    extern __shared__ char smem_raw[];
    __half* xsh = (__half*)smem_raw;                 // [128][XS_STRIDE]
    __half* bsm = xsh + XS_HALFS;                    // 2 x [KC][BS_STRIDE]
    const uint32_t sb_bs = smem_u32(bsm);

    const int tid  = threadIdx.x;
    const int lane = tid & 31;
    const int wid  = tid >> 5;
    const int wm   = wid & 3;            // 0..3 : 32-row slab
    const int wn   = wid >> 2;           // 0..1 : 32-col slab
    const int gid  = lane >> 2;          // 0..7
    const int tg   = lane & 3;           // 0..3
    const int m0 = (blockIdx.x & 31) * 128;
    const int n0 = (blockIdx.x >> 5) * 64;

    const __half* w1g = g_w1t;

    // ---- prefetch B chunk 0 (buf 0) ----
    #pragma unroll
    for (int r = 0; r < 2; r++) {
        int id = tid + r * 256;          // 0..511
        int row = id >> 3;               // 0..63 (n within tile)
        int seg = id & 7;                // 16B piece of 128B k-row
        cp_async16(sb_bs + (uint32_t)(row * (BS_STRIDE * 2) + seg * 16),
                   w1g + (size_t)(n0 + row) * KTOT + seg * 8);
    }
    CP_COMMIT();

    // ---- stage x tile as fp16 [m][j] ----
    #pragma unroll
    for (int r = 0; r < 16; r++) {
        int id = tid + r * 256;          // 0..4095 float4s
        int m = id >> 5, c4 = id & 31;
        float4 v = *(const float4*)(x + (size_t)(m0 + m) * DIM + c4 * 4);
        __half2 h0 = __floats2half2_rn(v.x, v.y);
        __half2 h1 = __floats2half2_rn(v.z, v.w);
        uint2 pk = make_uint2(*(uint32_t*)&h0, *(uint32_t*)&h1);
        *(uint2*)(xsh + m * XS_STRIDE + c4 * 4) = pk;
    }

    // per-thread global m rows for the 4 accumulator row-positions
    int rowt[4];
    rowt[0] = m0 + wm * 32 + gid;        // mt0, half0
    rowt[1] = rowt[0] + 8;               // mt0, half1
    rowt[2] = rowt[0] + 16;              // mt1, half0
    rowt[3] = rowt[0] + 24;              // mt1, half1

    float xc[4], xn[4];
    #pragma unroll
    for (int t = 0; t < 4; t++)
        xc[t] = 128.0f * __ldg(x + (size_t)rowt[t] * DIM);   // i = 0

    __syncthreads();

    float acc[2][4][4];
    float p[2][4][4];
    #pragma unroll
    for (int mt = 0; mt < 2; mt++)
        #pragma unroll
        for (int nt = 0; nt < 4; nt++)
            #pragma unroll
            for (int q = 0; q < 4; q++) acc[mt][nt][q] = 0.0f;

    #pragma unroll 1
    for (int it = 0; it < NCHUNK; it++) {
        // prefetch next chunk into the other buffer
        if (it + 1 < NCHUNK) {
            const uint32_t nb = (uint32_t)((it + 1) & 1) * (BS_STAGE_HALFS * 2);
            const int kbase = (it + 1) * KC;
            #pragma unroll
            for (int r = 0; r < 2; r++) {
                int id = tid + r * 256;
                int row = id >> 3;
                int seg = id & 7;
                cp_async16(sb_bs + nb + (uint32_t)(row * (BS_STRIDE * 2) + seg * 16),
                           w1g + (size_t)(n0 + row) * KTOT + kbase + seg * 8);
            }
            CP_COMMIT();
            CP_WAIT(1);
        } else {
            CP_WAIT(0);
        }
        __syncthreads();

        if ((it & 1) == 0) {
            // new i-block: zero partials, prefetch next i's x-column (exact f32)
            #pragma unroll
            for (int mt = 0; mt < 2; mt++)
                #pragma unroll
                for (int nt = 0; nt < 4; nt++)
                    #pragma unroll
                    for (int q = 0; q < 4; q++) p[mt][nt][q] = 0.0f;
            int inext = (it >> 1) + 1;
            if (inext < DIM) {
                #pragma unroll
                for (int t = 0; t < 4; t++)
                    xn[t] = 128.0f * __ldg(x + (size_t)rowt[t] * DIM + inext);
            }
        }

        const __half* bsf = bsm + (it & 1) * BS_STAGE_HALFS;
        const int j0 = (it & 1) << 6;

        #pragma unroll
        for (int s = 0; s < 4; s++) {    // 4 k16-steps per 64-k chunk
            uint32_t a[2][4];
            #pragma unroll
            for (int mt = 0; mt < 2; mt++) {
                const __half* ap = xsh + (wm * 32 + mt * 16 + gid) * XS_STRIDE
                                       + j0 + s * 16 + tg * 2;
                a[mt][0] = *(const uint32_t*)(ap);
                a[mt][1] = *(const uint32_t*)(ap + 8 * XS_STRIDE);
                a[mt][2] = *(const uint32_t*)(ap + 8);
                a[mt][3] = *(const uint32_t*)(ap + 8 * XS_STRIDE + 8);
            }
            const __half* bp = bsf + (wn * 32 + gid) * BS_STRIDE + s * 16 + tg * 2;
            #pragma unroll
            for (int nt = 0; nt < 4; nt++) {
                uint32_t b0 = *(const uint32_t*)(bp + nt * 8 * BS_STRIDE);
                uint32_t b1 = *(const uint32_t*)(bp + nt * 8 * BS_STRIDE + 8);
                MMA_F16(p[0][nt], a[0], b0, b1);
                MMA_F16(p[1][nt], a[1], b0, b1);
            }
        }

        if (it & 1) {
            // fold i-block: acc += (128*x_i[m]) * partial   (x_i exact f32)
            #pragma unroll
            for (int mt = 0; mt < 2; mt++)
                #pragma unroll
                for (int nt = 0; nt < 4; nt++) {
                    acc[mt][nt][0] = fmaf(xc[mt * 2],     p[mt][nt][0], acc[mt][nt][0]);
                    acc[mt][nt][1] = fmaf(xc[mt * 2],     p[mt][nt][1], acc[mt][nt][1]);
                    acc[mt][nt][2] = fmaf(xc[mt * 2 + 1], p[mt][nt][2], acc[mt][nt][2]);
                    acc[mt][nt][3] = fmaf(xc[mt * 2 + 1], p[mt][nt][3], acc[mt][nt][3]);
                }
            #pragma unroll
            for (int t = 0; t < 4; t++) xc[t] = xn[t];
        }
        __syncthreads();
    }

    // ---- Epilogue: +b1, relu, store h ----
    #pragma unroll
    for (int mt = 0; mt < 2; mt++) {
        #pragma unroll
        for (int nt = 0; nt < 4; nt++) {
            int col = n0 + wn * 32 + nt * 8 + tg * 2;
            float bb0 = bias1[col], bb1 = bias1[col + 1];
            int rowA = m0 + wm * 32 + mt * 16 + gid;
            float2 v0 = make_float2(fmaxf(acc[mt][nt][0] + bb0, 0.0f),
                                    fmaxf(acc[mt][nt][1] + bb1, 0.0f));
            float2 v1 = make_float2(fmaxf(acc[mt][nt][2] + bb0, 0.0f),
                                    fmaxf(acc[mt][nt][3] + bb1, 0.0f));
            *(float2*)(g_h + (size_t)rowA * HID + col) = v0;
            *(float2*)(g_h + (size_t)(rowA + 8) * HID + col) = v1;
        }
    }
}

// ----------------------------------------------------------------------------
// Kernel 3: out = h @ W2 + b2   [4096,512]x[512,256], packed f32x2 FMA
// ----------------------------------------------------------------------------
#define FMA2(acc, a, b) \
    asm("fma.rn.f32x2 %0, %1, %2, %0;" : "+l"(acc) : "l"(a), "l"(b))

__global__ __launch_bounds__(256) void k_layer2(const float* __restrict__ W2,
                                                const float* __restrict__ b2,
                                                float* __restrict__ out) {
    __shared__ float w2s[32 * 256];
    __shared__ float hs[32 * 32];
    const int tid = threadIdx.x;
    const int l = tid & 31;
    const int w = tid >> 5;
    const int m0 = blockIdx.x * 32;
    unsigned long long acc[4][4] = {};

    #pragma unroll 1
    for (int ch = 0; ch < 16; ch++) {
        #pragma unroll
        for (int r = 0; r < 8; r++) {
            int id = tid + r * 256;
            int rr = id >> 6, c4 = id & 63;
            *(float4*)(w2s + rr * 256 + c4 * 4) =
                *(const float4*)(W2 + (size_t)(ch * 32 + rr) * 256 + c4 * 4);
        }
        {
            int bl = tid >> 3, c4 = tid & 7;
            *(float4*)(hs + bl * 32 + c4 * 4) =
                *(const float4*)(g_h + (size_t)(m0 + bl) * HID + ch * 32 + c4 * 4);
        }
        __syncthreads();
        #pragma unroll 4
        for (int cc = 0; cc < 32; cc++) {
            ulonglong2 wA = *(const ulonglong2*)(w2s + cc * 256 + l * 4);
            ulonglong2 wB = *(const ulonglong2*)(w2s + cc * 256 + 128 + l * 4);
            #pragma unroll
            for (int bi = 0; bi < 4; bi++) {
                float hv = hs[(w * 4 + bi) * 32 + cc];
                unsigned long long hp;
                asm("mov.b64 %0, {%1, %1};" : "=l"(hp) : "f"(hv));
                FMA2(acc[bi][0], hp, wA.x);
                FMA2(acc[bi][1], hp, wA.y);
                FMA2(acc[bi][2], hp, wB.x);
                FMA2(acc[bi][3], hp, wB.y);
            }
        }
        __syncthreads();
    }
    float bA0 = b2[l * 4 + 0], bA1 = b2[l * 4 + 1], bA2 = b2[l * 4 + 2], bA3 = b2[l * 4 + 3];
    float bB0 = b2[128 + l * 4 + 0], bB1 = b2[128 + l * 4 + 1];
    float bB2 = b2[128 + l * 4 + 2], bB3 = b2[128 + l * 4 + 3];
    #pragma unroll
    for (int bi = 0; bi < 4; bi++) {
        int row = m0 + w * 4 + bi;
        float* orow = out + (size_t)row * 256;
        float f0, f1;
        asm("mov.b64 {%0, %1}, %2;" : "=f"(f0), "=f"(f1) : "l"(acc[bi][0]));
        *(float2*)(orow + l * 4) = make_float2(f0 + bA0, f1 + bA1);
        asm("mov.b64 {%0, %1}, %2;" : "=f"(f0), "=f"(f1) : "l"(acc[bi][1]));
        *(float2*)(orow + l * 4 + 2) = make_float2(f0 + bA2, f1 + bA3);
        asm("mov.b64 {%0, %1}, %2;" : "=f"(f0), "=f"(f1) : "l"(acc[bi][2]));
        *(float2*)(orow + 128 + l * 4) = make_float2(f0 + bB0, f1 + bB1);
        asm("mov.b64 {%0, %1}, %2;" : "=f"(f0), "=f"(f1) : "l"(acc[bi][3]));
        *(float2*)(orow + 128 + l * 4 + 2) = make_float2(f0 + bB2, f1 + bB3);
    }
}

// ----------------------------------------------------------------------------
// Launch
// ----------------------------------------------------------------------------
extern "C" void kernel_launch(void* const* d_in, const int* in_sizes, int n_in,
                              void* d_out, int out_size) {
    const float *x = nullptr, *W1 = nullptr, *b1 = nullptr, *W2 = nullptr, *b2 = nullptr;
    for (int i = 0; i < n_in; i++) {
        switch (in_sizes[i]) {
            case BATCH * DIM:  x  = (const float*)d_in[i]; break;   // 524288
            case KTOT * HID:   W1 = (const float*)d_in[i]; break;   // 8388608
            case HID:          b1 = (const float*)d_in[i]; break;   // 512
            case HID * OUTD:   W2 = (const float*)d_in[i]; break;   // 131072
            case OUTD:         b2 = (const float*)d_in[i]; break;   // 256
            default: break;
        }
    }

    cudaFuncSetAttribute(k_gemm1, cudaFuncAttributeMaxDynamicSharedMemorySize, G1_SMEM_BYTES);

    k_w1t<<<dim3(KTOT / 64, HID / 32), dim3(32, 8)>>>(W1);
    k_gemm1<<<256, 256, G1_SMEM_BYTES>>>(x, b1);
    k_layer2<<<BATCH / 32, 256>>>(W2, b2, (float*)d_out);
}

// round 8
// speedup vs baseline: 2.5858x; 1.1114x over previous
#include <cuda_runtime.h>
#include <cuda_fp16.h>
#include <cstdint>

// ----------------------------------------------------------------------------
// Problem constants
// ----------------------------------------------------------------------------
#define DIM 128            // input dim d
#define BATCH 4096
#define HID 512            // 2*OUTPUT_DIM
#define OUTD 256
#define KTOT (DIM * DIM)   // 16384
#define KC 128             // K chunk = one full i-block (j = 0..127)
#define NCHUNK (KTOT / KC) // 128
#define NSTAGE 3

// GEMM1 tiling: CTA 128(M) x 64(N), 8 warps (warp tile 32x32), 256 CTAs
#define XS_STRIDE 136      // fp16 x-tile row stride (halfs)  -> conflict-free ldmatrix
#define BS_STRIDE 136      // fp16 B-stage row stride (halfs) -> conflict-free ldmatrix
#define XS_HALFS (128 * XS_STRIDE)              // 17408 halfs = 34816 B
#define BS_STAGE_HALFS (64 * BS_STRIDE)         // 8704 halfs  = 17408 B
#define BS_STAGE_BYTES (BS_STAGE_HALFS * 2)
#define G1_SMEM_BYTES ((XS_HALFS + NSTAGE * BS_STAGE_HALFS) * 2)   // 87040 B

// ----------------------------------------------------------------------------
// Device scratch (static allocation: allowed)
// ----------------------------------------------------------------------------
__device__ __half g_w1t[HID * KTOT];     // W1^T in fp16, [n][k] layout (16.8MB)
__device__ float  g_h[BATCH * HID];      // hidden activations (8MB)

// ----------------------------------------------------------------------------
// Helpers
// ----------------------------------------------------------------------------
__device__ __forceinline__ uint32_t smem_u32(const void* p) {
    uint32_t a;
    asm("{ .reg .u64 t; cvta.to.shared.u64 t, %1; cvt.u32.u64 %0, t; }" : "=r"(a) : "l"(p));
    return a;
}
__device__ __forceinline__ void cp_async16(uint32_t smem_addr, const void* gptr) {
    asm volatile("cp.async.cg.shared.global [%0], [%1], 16;" :: "r"(smem_addr), "l"(gptr) : "memory");
}
#define CP_COMMIT() asm volatile("cp.async.commit_group;" ::: "memory")
#define CP_WAIT(n)  asm volatile("cp.async.wait_group %0;" :: "n"(n) : "memory")

// ldmatrix x4: 4 8x8 b16 matrices
#define LDSM4(r, addr) \
    asm volatile("ldmatrix.sync.aligned.m8n8.x4.shared.b16 {%0,%1,%2,%3}, [%4];" \
        : "=r"((r)[0]), "=r"((r)[1]), "=r"((r)[2]), "=r"((r)[3]) : "r"(addr))

// mma.sync m16n8k16 fp16, f32 accumulate (row.col)
#define MMA_F16(d, a, bb0, bb1) \
    asm volatile("mma.sync.aligned.m16n8k16.row.col.f32.f16.f16.f32 " \
        "{%0,%1,%2,%3}, {%4,%5,%6,%7}, {%8,%9}, {%0,%1,%2,%3};" \
        : "+f"((d)[0]), "+f"((d)[1]), "+f"((d)[2]), "+f"((d)[3]) \
        : "r"((a)[0]), "r"((a)[1]), "r"((a)[2]), "r"((a)[3]), "r"(bb0), "r"(bb1))

// ----------------------------------------------------------------------------
// Kernel 1: W1 [16384][512] f32  ->  g_w1t [512][16384] fp16 (transpose + cvt)
// ----------------------------------------------------------------------------
__global__ __launch_bounds__(256) void k_w1t(const float* __restrict__ W1) {
    __shared__ float t[32][66];
    const int kb = blockIdx.x * 64;
    const int nb = blockIdx.y * 32;
    const int tx = threadIdx.x, ty = threadIdx.y;
    #pragma unroll
    for (int r = 0; r < 8; r++) {
        int k = ty + r * 8;
        t[tx][k] = W1[(size_t)(kb + k) * HID + nb + tx];
    }
    __syncthreads();
    #pragma unroll
    for (int r = 0; r < 4; r++) {
        int n = ty + r * 8;
        __half2 h = __floats2half2_rn(t[n][tx * 2], t[n][tx * 2 + 1]);
        *(__half2*)(g_w1t + (size_t)(nb + n) * KTOT + kb + tx * 2) = h;
    }
}

// ----------------------------------------------------------------------------
// Kernel 2: H = relu( (d * x (x) x) @ W1 + b1 )
//   fp16 mma + ldmatrix, 3-stage cp.async ring, 1 barrier per chunk.
//   Chunk = one i-block: acc += (128*x_i) * ( fp16(x_j) @ W1[i*128 .. ) ).
// ----------------------------------------------------------------------------
__global__ __launch_bounds__(256, 2) void k_gemm1(const float* __restrict__ x,
                                                  const float* __restrict__ bias1) {
    extern __shared__ char smem_raw[];
    __half* xsh = (__half*)smem_raw;                 // [128][XS_STRIDE]
    __half* bsm = xsh + XS_HALFS;                    // NSTAGE x [64][BS_STRIDE]
    const uint32_t xs_b = smem_u32(xsh);
    const uint32_t bs_b = smem_u32(bsm);

    const int tid  = threadIdx.x;
    const int lane = tid & 31;
    const int wid  = tid >> 5;
    const int wm   = wid & 3;            // 0..3 : 32-row slab
    const int wn   = wid >> 2;           // 0..1 : 32-col slab
    const int gid  = lane >> 2;          // 0..7
    const int tg   = lane & 3;           // 0..3
    const int m0 = (blockIdx.x & 31) * 128;
    const int n0 = (blockIdx.x >> 5) * 64;

    const __half* w1g = g_w1t;

    // ---- prefetch B stages 0 and 1 ----
    #pragma unroll
    for (int st = 0; st < 2; st++) {
        const int kbase = st * KC;
        #pragma unroll
        for (int r = 0; r < 4; r++) {
            int id = tid + r * 256;          // 0..1023
            int row = id >> 4;               // 0..63
            int seg = id & 15;               // 16B piece of 256B k-row
            cp_async16(bs_b + (uint32_t)(st * BS_STAGE_BYTES + row * (BS_STRIDE * 2) + seg * 16),
                       w1g + (size_t)(n0 + row) * KTOT + kbase + seg * 8);
        }
        CP_COMMIT();
    }

    // ---- stage x tile as fp16 [m][j] ----
    #pragma unroll
    for (int r = 0; r < 16; r++) {
        int id = tid + r * 256;
        int m = id >> 5, c4 = id & 31;
        float4 v = *(const float4*)(x + (size_t)(m0 + m) * DIM + c4 * 4);
        __half2 h0 = __floats2half2_rn(v.x, v.y);
        __half2 h1 = __floats2half2_rn(v.z, v.w);
        uint2 pk = make_uint2(*(uint32_t*)&h0, *(uint32_t*)&h1);
        *(uint2*)(xsh + m * XS_STRIDE + c4 * 4) = pk;
    }

    // per-thread global m rows for the 4 accumulator row-positions
    int rowt[4];
    rowt[0] = m0 + wm * 32 + gid;
    rowt[1] = rowt[0] + 8;
    rowt[2] = rowt[0] + 16;
    rowt[3] = rowt[0] + 24;

    // ldmatrix per-lane base addresses
    const int l7 = lane & 7;
    // A: bit3 -> +8 rows, bit4 -> +8 cols
    const uint32_t aAddr = xs_b +
        (uint32_t)(((wm * 32 + l7 + ((lane >> 3) & 1) * 8) * XS_STRIDE + ((lane >> 4) & 1) * 8) * 2);
    // B: bit4 -> +8 rows (n), bit3 -> +8 cols (k)
    const uint32_t bAddr = bs_b +
        (uint32_t)(((wn * 32 + l7 + ((lane >> 4) & 1) * 8) * BS_STRIDE + ((lane >> 3) & 1) * 8) * 2);

    float acc[2][4][4];
    #pragma unroll
    for (int mt = 0; mt < 2; mt++)
        #pragma unroll
        for (int nt = 0; nt < 4; nt++)
            #pragma unroll
            for (int q = 0; q < 4; q++) acc[mt][nt][q] = 0.0f;

    __syncthreads();

    #pragma unroll 1
    for (int it = 0; it < NCHUNK; it++) {
        CP_WAIT(1);
        __syncthreads();

        // prefetch chunk it+2 into buffer (it+2)%3
        if (it + 2 < NCHUNK) {
            const uint32_t buf = (uint32_t)((it + 2) % NSTAGE) * BS_STAGE_BYTES;
            const int kbase = (it + 2) * KC;
            #pragma unroll
            for (int r = 0; r < 4; r++) {
                int id = tid + r * 256;
                int row = id >> 4;
                int seg = id & 15;
                cp_async16(bs_b + buf + (uint32_t)(row * (BS_STRIDE * 2) + seg * 16),
                           w1g + (size_t)(n0 + row) * KTOT + kbase + seg * 8);
            }
        }
        CP_COMMIT();

        // exact f32 scale for this i-block
        float xi[4];
        #pragma unroll
        for (int t = 0; t < 4; t++)
            xi[t] = 128.0f * __ldg(x + (size_t)rowt[t] * DIM + it);

        const uint32_t bStage = bAddr + (uint32_t)(it % NSTAGE) * BS_STAGE_BYTES;

        float p[2][4][4];
        #pragma unroll
        for (int mt = 0; mt < 2; mt++)
            #pragma unroll
            for (int nt = 0; nt < 4; nt++)
                #pragma unroll
                for (int q = 0; q < 4; q++) p[mt][nt][q] = 0.0f;

        #pragma unroll
        for (int s = 0; s < 8; s++) {    // 8 k16-steps covering j = 0..127
            uint32_t a0[4], a1[4], bA[4], bB[4];
            LDSM4(a0, aAddr + (uint32_t)(s * 32));
            LDSM4(a1, aAddr + (uint32_t)(16 * XS_STRIDE * 2 + s * 32));
            LDSM4(bA, bStage + (uint32_t)(s * 32));
            LDSM4(bB, bStage + (uint32_t)(16 * BS_STRIDE * 2 + s * 32));
            MMA_F16(p[0][0], a0, bA[0], bA[1]);
            MMA_F16(p[1][0], a1, bA[0], bA[1]);
            MMA_F16(p[0][1], a0, bA[2], bA[3]);
            MMA_F16(p[1][1], a1, bA[2], bA[3]);
            MMA_F16(p[0][2], a0, bB[0], bB[1]);
            MMA_F16(p[1][2], a1, bB[0], bB[1]);
            MMA_F16(p[0][3], a0, bB[2], bB[3]);
            MMA_F16(p[1][3], a1, bB[2], bB[3]);
        }

        // fold: acc += (128*x_i[m]) * partial
        #pragma unroll
        for (int mt = 0; mt < 2; mt++)
            #pragma unroll
            for (int nt = 0; nt < 4; nt++) {
                acc[mt][nt][0] = fmaf(xi[mt * 2],     p[mt][nt][0], acc[mt][nt][0]);
                acc[mt][nt][1] = fmaf(xi[mt * 2],     p[mt][nt][1], acc[mt][nt][1]);
                acc[mt][nt][2] = fmaf(xi[mt * 2 + 1], p[mt][nt][2], acc[mt][nt][2]);
                acc[mt][nt][3] = fmaf(xi[mt * 2 + 1], p[mt][nt][3], acc[mt][nt][3]);
            }
    }

    // ---- Epilogue: +b1, relu, store h ----
    #pragma unroll
    for (int mt = 0; mt < 2; mt++) {
        #pragma unroll
        for (int nt = 0; nt < 4; nt++) {
            int col = n0 + wn * 32 + nt * 8 + tg * 2;
            float bb0 = bias1[col], bb1 = bias1[col + 1];
            int rowA = m0 + wm * 32 + mt * 16 + gid;
            float2 v0 = make_float2(fmaxf(acc[mt][nt][0] + bb0, 0.0f),
                                    fmaxf(acc[mt][nt][1] + bb1, 0.0f));
            float2 v1 = make_float2(fmaxf(acc[mt][nt][2] + bb0, 0.0f),
                                    fmaxf(acc[mt][nt][3] + bb1, 0.0f));
            *(float2*)(g_h + (size_t)rowA * HID + col) = v0;
            *(float2*)(g_h + (size_t)(rowA + 8) * HID + col) = v1;
        }
    }
}

// ----------------------------------------------------------------------------
// Kernel 3: out = h @ W2 + b2   [4096,512]x[512,256], packed f32x2 FMA
// ----------------------------------------------------------------------------
#define FMA2(acc, a, b) \
    asm("fma.rn.f32x2 %0, %1, %2, %0;" : "+l"(acc) : "l"(a), "l"(b))

__global__ __launch_bounds__(256) void k_layer2(const float* __restrict__ W2,
                                                const float* __restrict__ b2,
                                                float* __restrict__ out) {
    __shared__ float w2s[32 * 256];
    __shared__ float hs[32 * 32];
    const int tid = threadIdx.x;
    const int l = tid & 31;
    const int w = tid >> 5;
    const int m0 = blockIdx.x * 32;
    unsigned long long acc[4][4] = {};

    #pragma unroll 1
    for (int ch = 0; ch < 16; ch++) {
        #pragma unroll
        for (int r = 0; r < 8; r++) {
            int id = tid + r * 256;
            int rr = id >> 6, c4 = id & 63;
            *(float4*)(w2s + rr * 256 + c4 * 4) =
                *(const float4*)(W2 + (size_t)(ch * 32 + rr) * 256 + c4 * 4);
        }
        {
            int bl = tid >> 3, c4 = tid & 7;
            *(float4*)(hs + bl * 32 + c4 * 4) =
                *(const float4*)(g_h + (size_t)(m0 + bl) * HID + ch * 32 + c4 * 4);
        }
        __syncthreads();
        #pragma unroll 4
        for (int cc = 0; cc < 32; cc++) {
            ulonglong2 wA = *(const ulonglong2*)(w2s + cc * 256 + l * 4);
            ulonglong2 wB = *(const ulonglong2*)(w2s + cc * 256 + 128 + l * 4);
            #pragma unroll
            for (int bi = 0; bi < 4; bi++) {
                float hv = hs[(w * 4 + bi) * 32 + cc];
                unsigned long long hp;
                asm("mov.b64 %0, {%1, %1};" : "=l"(hp) : "f"(hv));
                FMA2(acc[bi][0], hp, wA.x);
                FMA2(acc[bi][1], hp, wA.y);
                FMA2(acc[bi][2], hp, wB.x);
                FMA2(acc[bi][3], hp, wB.y);
            }
        }
        __syncthreads();
    }
    float bA0 = b2[l * 4 + 0], bA1 = b2[l * 4 + 1], bA2 = b2[l * 4 + 2], bA3 = b2[l * 4 + 3];
    float bB0 = b2[128 + l * 4 + 0], bB1 = b2[128 + l * 4 + 1];
    float bB2 = b2[128 + l * 4 + 2], bB3 = b2[128 + l * 4 + 3];
    #pragma unroll
    for (int bi = 0; bi < 4; bi++) {
        int row = m0 + w * 4 + bi;
        float* orow = out + (size_t)row * 256;
        float f0, f1;
        asm("mov.b64 {%0, %1}, %2;" : "=f"(f0), "=f"(f1) : "l"(acc[bi][0]));
        *(float2*)(orow + l * 4) = make_float2(f0 + bA0, f1 + bA1);
        asm("mov.b64 {%0, %1}, %2;" : "=f"(f0), "=f"(f1) : "l"(acc[bi][1]));
        *(float2*)(orow + l * 4 + 2) = make_float2(f0 + bA2, f1 + bA3);
        asm("mov.b64 {%0, %1}, %2;" : "=f"(f0), "=f"(f1) : "l"(acc[bi][2]));
        *(float2*)(orow + 128 + l * 4) = make_float2(f0 + bB0, f1 + bB1);
        asm("mov.b64 {%0, %1}, %2;" : "=f"(f0), "=f"(f1) : "l"(acc[bi][3]));
        *(float2*)(orow + 128 + l * 4 + 2) = make_float2(f0 + bB2, f1 + bB3);
    }
}

// ----------------------------------------------------------------------------
// Launch
// ----------------------------------------------------------------------------
extern "C" void kernel_launch(void* const* d_in, const int* in_sizes, int n_in,
                              void* d_out, int out_size) {
    const float *x = nullptr, *W1 = nullptr, *b1 = nullptr, *W2 = nullptr, *b2 = nullptr;
    for (int i = 0; i < n_in; i++) {
        switch (in_sizes[i]) {
            case BATCH * DIM:  x  = (const float*)d_in[i]; break;   // 524288
            case KTOT * HID:   W1 = (const float*)d_in[i]; break;   // 8388608
            case HID:          b1 = (const float*)d_in[i]; break;   // 512
            case HID * OUTD:   W2 = (const float*)d_in[i]; break;   // 131072
            case OUTD:         b2 = (const float*)d_in[i]; break;   // 256
            default: break;
        }
    }

    cudaFuncSetAttribute(k_gemm1, cudaFuncAttributeMaxDynamicSharedMemorySize, G1_SMEM_BYTES);

    k_w1t<<<dim3(KTOT / 64, HID / 32), dim3(32, 8)>>>(W1);
    k_gemm1<<<256, 256, G1_SMEM_BYTES>>>(x, b1);
    k_layer2<<<BATCH / 32, 256>>>(W2, b2, (float*)d_out);
}

// round 11
// speedup vs baseline: 3.4500x; 1.3342x over previous
#include <cuda_runtime.h>
#include <cuda_fp16.h>
#include <cstdint>

// ----------------------------------------------------------------------------
// Problem constants
// ----------------------------------------------------------------------------
#define DIM 128            // input dim d
#define BATCH 4096
#define HID 512            // 2*OUTPUT_DIM
#define OUTD 256
#define KTOT (DIM * DIM)   // 16384
#define KC 128             // K chunk = one full i-block (j = 0..127)
#define NCHUNK (KTOT / KC) // 128
#define NSTAGE 3

// GEMM1 tiling: CTA 128(M) x 64(N), 8 warps (warp tile 32x32), 256 CTAs
#define XS_STRIDE 136      // fp16 x-tile row stride (halfs)  -> conflict-free ldmatrix
#define BS_STRIDE 136      // fp16 B-stage row stride (halfs) -> conflict-free ldmatrix
#define XS_HALFS (128 * XS_STRIDE)              // 17408 halfs = 34816 B
#define BS_STAGE_HALFS (64 * BS_STRIDE)         // 8704 halfs  = 17408 B
#define BS_STAGE_BYTES (BS_STAGE_HALFS * 2)
#define G1_SMEM_BYTES ((XS_HALFS + NSTAGE * BS_STAGE_HALFS) * 2)   // 87040 B

// ----------------------------------------------------------------------------
// Device scratch (static allocation: allowed)
// ----------------------------------------------------------------------------
// W1sym^T in fp16, [n][k] layout, k=(i,j):  j>i: W1[ij]+W1[ji], j==i: W1[ii], j<i: 0
__device__ __half g_w1t[HID * KTOT];     // 16.8MB
__device__ float  g_h[BATCH * HID];      // hidden activations (8MB)

// ----------------------------------------------------------------------------
// Helpers
// ----------------------------------------------------------------------------
__device__ __forceinline__ uint32_t smem_u32(const void* p) {
    uint32_t a;
    asm("{ .reg .u64 t; cvta.to.shared.u64 t, %1; cvt.u32.u64 %0, t; }" : "=r"(a) : "l"(p));
    return a;
}
__device__ __forceinline__ void cp_async16(uint32_t smem_addr, const void* gptr) {
    asm volatile("cp.async.cg.shared.global [%0], [%1], 16;" :: "r"(smem_addr), "l"(gptr) : "memory");
}
#define CP_COMMIT() asm volatile("cp.async.commit_group;" ::: "memory")
#define CP_WAIT(n)  asm volatile("cp.async.wait_group %0;" :: "n"(n) : "memory")

// ldmatrix x4: 4 8x8 b16 matrices
#define LDSM4(r, addr) \
    asm volatile("ldmatrix.sync.aligned.m8n8.x4.shared.b16 {%0,%1,%2,%3}, [%4];" \
        : "=r"((r)[0]), "=r"((r)[1]), "=r"((r)[2]), "=r"((r)[3]) : "r"(addr))

// mma.sync m16n8k16 fp16, f32 accumulate (row.col)
#define MMA_F16(d, a, bb0, bb1) \
    asm volatile("mma.sync.aligned.m16n8k16.row.col.f32.f16.f16.f32 " \
        "{%0,%1,%2,%3}, {%4,%5,%6,%7}, {%8,%9}, {%0,%1,%2,%3};" \
        : "+f"((d)[0]), "+f"((d)[1]), "+f"((d)[2]), "+f"((d)[3]) \
        : "r"((a)[0]), "r"((a)[1]), "r"((a)[2]), "r"((a)[3]), "r"(bb0), "r"(bb1))

// ----------------------------------------------------------------------------
// Kernel 1: symmetrize + transpose + fp16-convert W1.
//   g_w1t[n][i*128+j] = (j>i) ? W1[i*128+j][n]+W1[j*128+i][n]
//                     : (j==i)? W1[i*128+i][n] : 0
//   grid (128 i, 16 n-tiles), block (32,8)
// ----------------------------------------------------------------------------
__global__ __launch_bounds__(256) void k_w1sym(const float* __restrict__ W1) {
    __shared__ float ssum[128][33];
    const int i  = blockIdx.x;           // 0..127
    const int nb = blockIdx.y * 32;
    const int tx = threadIdx.x, ty = threadIdx.y;
    #pragma unroll
    for (int r = 0; r < 16; r++) {
        int j = ty + r * 8;
        float v = 0.0f;
        if (j > i) {
            v = W1[(size_t)(i * DIM + j) * HID + nb + tx]
              + W1[(size_t)(j * DIM + i) * HID + nb + tx];
        } else if (j == i) {
            v = W1[(size_t)(i * DIM + i) * HID + nb + tx];
        }
        ssum[j][tx] = v;
    }
    __syncthreads();
    #pragma unroll
    for (int r = 0; r < 4; r++) {
        int n = ty + r * 8;
        int j4 = tx * 4;
        __half2 h0 = __floats2half2_rn(ssum[j4 + 0][n], ssum[j4 + 1][n]);
        __half2 h1 = __floats2half2_rn(ssum[j4 + 2][n], ssum[j4 + 3][n]);
        uint2 pk = make_uint2(*(uint32_t*)&h0, *(uint32_t*)&h1);
        *(uint2*)(g_w1t + (size_t)(nb + n) * KTOT + i * DIM + j4) = pk;
    }
}

// ----------------------------------------------------------------------------
// Kernel 2: H = relu( (d * x (x) x) @ W1 + b1 ) using the symmetric triangle:
//   acc += (128*x_i) * ( fp16(x_j) @ W1sym[i, j>=i] ),  j-loop starts at
//   16-aligned floor of i (sub-diagonal entries of W1sym are zero).
// ----------------------------------------------------------------------------
__global__ __launch_bounds__(256, 2) void k_gemm1(const float* __restrict__ x,
                                                  const float* __restrict__ bias1) {
    extern __shared__ char smem_raw[];
    __half* xsh = (__half*)smem_raw;                 // [128][XS_STRIDE]
    __half* bsm = xsh + XS_HALFS;                    // NSTAGE x [64][BS_STRIDE]
    const uint32_t xs_b = smem_u32(xsh);
    const uint32_t bs_b = smem_u32(bsm);

    const int tid  = threadIdx.x;
    const int lane = tid & 31;
    const int wid  = tid >> 5;
    const int wm   = wid & 3;            // 0..3 : 32-row slab
    const int wn   = wid >> 2;           // 0..1 : 32-col slab
    const int gid  = lane >> 2;          // 0..7
    const int tg   = lane & 3;           // 0..3
    const int m0 = (blockIdx.x & 31) * 128;
    const int n0 = (blockIdx.x >> 5) * 64;

    const __half* w1g = g_w1t;

    // ---- prefetch B stages 0 and 1 (chunks 0,1: full 128-j range) ----
    #pragma unroll
    for (int st = 0; st < 2; st++) {
        const int kbase = st * KC;
        #pragma unroll
        for (int r = 0; r < 4; r++) {
            int id = tid + r * 256;          // 0..1023
            int row = id >> 4;               // 0..63
            int seg = id & 15;               // 16B piece of 256B k-row
            cp_async16(bs_b + (uint32_t)(st * BS_STAGE_BYTES + row * (BS_STRIDE * 2) + seg * 16),
                       w1g + (size_t)(n0 + row) * KTOT + kbase + seg * 8);
        }
        CP_COMMIT();
    }

    // ---- stage x tile as fp16 [m][j] ----
    #pragma unroll
    for (int r = 0; r < 16; r++) {
        int id = tid + r * 256;
        int m = id >> 5, c4 = id & 31;
        float4 v = *(const float4*)(x + (size_t)(m0 + m) * DIM + c4 * 4);
        __half2 h0 = __floats2half2_rn(v.x, v.y);
        __half2 h1 = __floats2half2_rn(v.z, v.w);
        uint2 pk = make_uint2(*(uint32_t*)&h0, *(uint32_t*)&h1);
        *(uint2*)(xsh + m * XS_STRIDE + c4 * 4) = pk;
    }

    // per-thread global m rows for the 4 accumulator row-positions
    int rowt[4];
    rowt[0] = m0 + wm * 32 + gid;
    rowt[1] = rowt[0] + 8;
    rowt[2] = rowt[0] + 16;
    rowt[3] = rowt[0] + 24;

    // ldmatrix per-lane base addresses
    const int l7 = lane & 7;
    const uint32_t aAddr = xs_b +
        (uint32_t)(((wm * 32 + l7 + ((lane >> 3) & 1) * 8) * XS_STRIDE + ((lane >> 4) & 1) * 8) * 2);
    const uint32_t bAddr = bs_b +
        (uint32_t)(((wn * 32 + l7 + ((lane >> 4) & 1) * 8) * BS_STRIDE + ((lane >> 3) & 1) * 8) * 2);

    float acc[2][4][4];
    #pragma unroll
    for (int mt = 0; mt < 2; mt++)
        #pragma unroll
        for (int nt = 0; nt < 4; nt++)
            #pragma unroll
            for (int q = 0; q < 4; q++) acc[mt][nt][q] = 0.0f;

    __syncthreads();

    #pragma unroll 1
    for (int it = 0; it < NCHUNK; it++) {
        CP_WAIT(1);
        __syncthreads();

        // prefetch chunk it+2 into buffer (it+2)%3 — only segs covering j >= 16*floor(i/16)
        if (it + 2 < NCHUNK) {
            const int c = it + 2;
            const int smin = (c >> 4) * 2;                 // first 16B seg needed
            const uint32_t buf = (uint32_t)(c % NSTAGE) * BS_STAGE_BYTES;
            const int kbase = c * KC;
            #pragma unroll
            for (int r = 0; r < 4; r++) {
                int id = tid + r * 256;
                int row = id >> 4;
                int seg = id & 15;
                if (seg >= smin)
                    cp_async16(bs_b + buf + (uint32_t)(row * (BS_STRIDE * 2) + seg * 16),
                               w1g + (size_t)(n0 + row) * KTOT + kbase + seg * 8);
            }
        }
        CP_COMMIT();

        // exact f32 scale for this i-block
        float xi[4];
        #pragma unroll
        for (int t = 0; t < 4; t++)
            xi[t] = 128.0f * __ldg(x + (size_t)rowt[t] * DIM + it);

        const uint32_t bStage = bAddr + (uint32_t)(it % NSTAGE) * BS_STAGE_BYTES;

        float p[2][4][4];
        #pragma unroll
        for (int mt = 0; mt < 2; mt++)
            #pragma unroll
            for (int nt = 0; nt < 4; nt++)
                #pragma unroll
                for (int q = 0; q < 4; q++) p[mt][nt][q] = 0.0f;

        const int s0 = it >> 4;          // triangle: skip j-blocks entirely below diagonal
        for (int s = s0; s < 8; s++) {
            uint32_t a0[4], a1[4], bA[4], bB[4];
            LDSM4(a0, aAddr + (uint32_t)(s * 32));
            LDSM4(a1, aAddr + (uint32_t)(16 * XS_STRIDE * 2 + s * 32));
            LDSM4(bA, bStage + (uint32_t)(s * 32));
            LDSM4(bB, bStage + (uint32_t)(16 * BS_STRIDE * 2 + s * 32));
            MMA_F16(p[0][0], a0, bA[0], bA[1]);
            MMA_F16(p[1][0], a1, bA[0], bA[1]);
            MMA_F16(p[0][1], a0, bA[2], bA[3]);
            MMA_F16(p[1][1], a1, bA[2], bA[3]);
            MMA_F16(p[0][2], a0, bB[0], bB[1]);
            MMA_F16(p[1][2], a1, bB[0], bB[1]);
            MMA_F16(p[0][3], a0, bB[2], bB[3]);
            MMA_F16(p[1][3], a1, bB[2], bB[3]);
        }

        // fold: acc += (128*x_i[m]) * partial
        #pragma unroll
        for (int mt = 0; mt < 2; mt++)
            #pragma unroll
            for (int nt = 0; nt < 4; nt++) {
                acc[mt][nt][0] = fmaf(xi[mt * 2],     p[mt][nt][0], acc[mt][nt][0]);
                acc[mt][nt][1] = fmaf(xi[mt * 2],     p[mt][nt][1], acc[mt][nt][1]);
                acc[mt][nt][2] = fmaf(xi[mt * 2 + 1], p[mt][nt][2], acc[mt][nt][2]);
                acc[mt][nt][3] = fmaf(xi[mt * 2 + 1], p[mt][nt][3], acc[mt][nt][3]);
            }
    }

    // ---- Epilogue: +b1, relu, store h ----
    #pragma unroll
    for (int mt = 0; mt < 2; mt++) {
        #pragma unroll
        for (int nt = 0; nt < 4; nt++) {
            int col = n0 + wn * 32 + nt * 8 + tg * 2;
            float bb0 = bias1[col], bb1 = bias1[col + 1];
            int rowA = m0 + wm * 32 + mt * 16 + gid;
            float2 v0 = make_float2(fmaxf(acc[mt][nt][0] + bb0, 0.0f),
                                    fmaxf(acc[mt][nt][1] + bb1, 0.0f));
            float2 v1 = make_float2(fmaxf(acc[mt][nt][2] + bb0, 0.0f),
                                    fmaxf(acc[mt][nt][3] + bb1, 0.0f));
            *(float2*)(g_h + (size_t)rowA * HID + col) = v0;
            *(float2*)(g_h + (size_t)(rowA + 8) * HID + col) = v1;
        }
    }
}

// ----------------------------------------------------------------------------
// Kernel 3: out = h @ W2 + b2   [4096,512]x[512,256], packed f32x2 FMA
// ----------------------------------------------------------------------------
#define FMA2(acc, a, b) \
    asm("fma.rn.f32x2 %0, %1, %2, %0;" : "+l"(acc) : "l"(a), "l"(b))

__global__ __launch_bounds__(256) void k_layer2(const float* __restrict__ W2,
                                                const float* __restrict__ b2,
                                                float* __restrict__ out) {
    __shared__ float w2s[32 * 256];
    __shared__ float hs[32 * 32];
    const int tid = threadIdx.x;
    const int l = tid & 31;
    const int w = tid >> 5;
    const int m0 = blockIdx.x * 32;
    unsigned long long acc[4][4] = {};

    #pragma unroll 1
    for (int ch = 0; ch < 16; ch++) {
        #pragma unroll
        for (int r = 0; r < 8; r++) {
            int id = tid + r * 256;
            int rr = id >> 6, c4 = id & 63;
            *(float4*)(w2s + rr * 256 + c4 * 4) =
                *(const float4*)(W2 + (size_t)(ch * 32 + rr) * 256 + c4 * 4);
        }
        {
            int bl = tid >> 3, c4 = tid & 7;
            *(float4*)(hs + bl * 32 + c4 * 4) =
                *(const float4*)(g_h + (size_t)(m0 + bl) * HID + ch * 32 + c4 * 4);
        }
        __syncthreads();
        #pragma unroll 4
        for (int cc = 0; cc < 32; cc++) {
            ulonglong2 wA = *(const ulonglong2*)(w2s + cc * 256 + l * 4);
            ulonglong2 wB = *(const ulonglong2*)(w2s + cc * 256 + 128 + l * 4);
            #pragma unroll
            for (int bi = 0; bi < 4; bi++) {
                float hv = hs[(w * 4 + bi) * 32 + cc];
                unsigned long long hp;
                asm("mov.b64 %0, {%1, %1};" : "=l"(hp) : "f"(hv));
                FMA2(acc[bi][0], hp, wA.x);
                FMA2(acc[bi][1], hp, wA.y);
                FMA2(acc[bi][2], hp, wB.x);
                FMA2(acc[bi][3], hp, wB.y);
            }
        }
        __syncthreads();
    }
    float bA0 = b2[l * 4 + 0], bA1 = b2[l * 4 + 1], bA2 = b2[l * 4 + 2], bA3 = b2[l * 4 + 3];
    float bB0 = b2[128 + l * 4 + 0], bB1 = b2[128 + l * 4 + 1];
    float bB2 = b2[128 + l * 4 + 2], bB3 = b2[128 + l * 4 + 3];
    #pragma unroll
    for (int bi = 0; bi < 4; bi++) {
        int row = m0 + w * 4 + bi;
        float* orow = out + (size_t)row * 256;
        float f0, f1;
        asm("mov.b64 {%0, %1}, %2;" : "=f"(f0), "=f"(f1) : "l"(acc[bi][0]));
        *(float2*)(orow + l * 4) = make_float2(f0 + bA0, f1 + bA1);
        asm("mov.b64 {%0, %1}, %2;" : "=f"(f0), "=f"(f1) : "l"(acc[bi][1]));
        *(float2*)(orow + l * 4 + 2) = make_float2(f0 + bA2, f1 + bA3);
        asm("mov.b64 {%0, %1}, %2;" : "=f"(f0), "=f"(f1) : "l"(acc[bi][2]));
        *(float2*)(orow + 128 + l * 4) = make_float2(f0 + bB0, f1 + bB1);
        asm("mov.b64 {%0, %1}, %2;" : "=f"(f0), "=f"(f1) : "l"(acc[bi][3]));
        *(float2*)(orow + 128 + l * 4 + 2) = make_float2(f0 + bB2, f1 + bB3);
    }
}

// ----------------------------------------------------------------------------
// Launch
// ----------------------------------------------------------------------------
extern "C" void kernel_launch(void* const* d_in, const int* in_sizes, int n_in,
                              void* d_out, int out_size) {
    const float *x = nullptr, *W1 = nullptr, *b1 = nullptr, *W2 = nullptr, *b2 = nullptr;
    for (int i = 0; i < n_in; i++) {
        switch (in_sizes[i]) {
            case BATCH * DIM:  x  = (const float*)d_in[i]; break;   // 524288
            case KTOT * HID:   W1 = (const float*)d_in[i]; break;   // 8388608
            case HID:          b1 = (const float*)d_in[i]; break;   // 512
            case HID * OUTD:   W2 = (const float*)d_in[i]; break;   // 131072
            case OUTD:         b2 = (const float*)d_in[i]; break;   // 256
            default: break;
        }
    }

    cudaFuncSetAttribute(k_gemm1, cudaFuncAttributeMaxDynamicSharedMemorySize, G1_SMEM_BYTES);

    k_w1sym<<<dim3(DIM, HID / 32), dim3(32, 8)>>>(W1);
    k_gemm1<<<256, 256, G1_SMEM_BYTES>>>(x, b1);
    k_layer2<<<BATCH / 32, 256>>>(W2, b2, (float*)d_out);
}